// round 14
// baseline (speedup 1.0000x reference)
#include <cuda_runtime.h>
#include <cuda_bf16.h>
#include <cstdint>

// MolecularGraphNeuralNetwork — v11: 2 molecules/CTA, warp-local norms.
//
// 128 CTAs x 128 threads. Warp w -> molecule (w>>1), atom half (w&1):
// one m16 A-tile (16 atoms) x ALL 64 dims (8 n-tiles). Consequences:
//   - L2 norm is warp-local (tig-group spans all 64 dims): ssP barrier gone,
//     2 barriers/layer instead of 3.
//   - 128 CTAs <= 148 SMs: one CTA/SM, no 2-CTA straggler SMs.
//   - molecular sum computed from fragments via shfl (vP array gone).
// MLP : D1 = V@W^T, 3-term bf16 split. Prop: D2 = (A+I)@H, 2-term split
// (A exact in bf16). Fragment layouts identical to the round-10/13 verified
// addressing (half replaces wm; nt extended 4->8).

#define T_ATOMS 8192
#define B_MOL   256
#define APM     32
#define DIM     64
#define LH      3
#define BFP     72   // V/W bf16 rows: 144 B
#define HTP     40   // hT/A bf16 rows: 80 B

struct SmemLayout {
    float sBias[LH * DIM];
    float molP[2][2][DIM];          // [mol][half][dim] partial sums
    float molA[2][DIM];
    float molB[2][DIM];
    __nv_bfloat16 hThi[2][DIM][HTP];   // per-mol hT[d][j] = h[j][d]
    __nv_bfloat16 hTlo[2][DIM][HTP];
    __nv_bfloat16 Abf[2][APM][HTP];    // per-mol (A+I), exact bf16
    __nv_bfloat16 Vhi[2][APM][BFP];
    __nv_bfloat16 Vlo[2][APM][BFP];
    __nv_bfloat16 Whi[DIM][BFP];       // shared by both molecules
    __nv_bfloat16 Wlo[DIM][BFP];
};

#define MMA_BF16(d0,d1,d2,d3,a0,a1,a2,a3,b0,b1)                          \
    asm volatile("mma.sync.aligned.m16n8k16.row.col.f32.bf16.bf16.f32 "  \
        "{%0,%1,%2,%3}, {%4,%5,%6,%7}, {%8,%9}, {%0,%1,%2,%3};"          \
        : "+f"(d0), "+f"(d1), "+f"(d2), "+f"(d3)                          \
        : "r"(a0), "r"(a1), "r"(a2), "r"(a3), "r"(b0), "r"(b1))

__device__ __forceinline__ uint32_t lds_u32(const __nv_bfloat16* base, int byteOff) {
    return *reinterpret_cast<const uint32_t*>(
        reinterpret_cast<const char*>(base) + byteOff);
}

__global__ __launch_bounds__(128)
void gnn_mol_kernel(const int*   __restrict__ fp,
                    const float* __restrict__ adj,
                    const float* __restrict__ embed,
                    const float* __restrict__ W_fp,
                    const float* __restrict__ b_fp,
                    const float* __restrict__ W_out,
                    const float* __restrict__ b_out,
                    const float* __restrict__ W_prop,
                    const float* __restrict__ b_prop,
                    float*       __restrict__ out)
{
    extern __shared__ char smem_raw[];
    SmemLayout& S = *reinterpret_cast<SmemLayout*>(smem_raw);

    const int bid  = blockIdx.x;        // molecules 2*bid, 2*bid+1
    const int tid  = threadIdx.x;
    const int lane = tid & 31;
    const int g    = tid >> 5;
    const int s    = g >> 1;            // molecule slot (0/1)
    const int half = g & 1;             // atom half (rows 16*half..+15)
    const int g4   = lane >> 2;         // mma group id
    const int tig  = lane & 3;          // thread-in-group
    const int r0   = 16 * half + g4;    // mma output rows (atoms in mol)
    const int r1   = r0 + 8;
    const int mm   = 2 * bid + s;       // global molecule id

    // ================= init =================
    if (tid < LH * DIM) S.sBias[tid] = b_fp[tid];
    if (tid + 128 < LH * DIM) S.sBias[tid + 128] = b_fp[tid + 128];

    // (A+I) for both molecules -> exact bf16 (2048 entries, 16/thread)
    #pragma unroll
    for (int t = 0; t < 16; t++) {
        const int e = tid + t * 128;
        const int sl = e >> 10, r = (e >> 5) & 31, c = e & 31;
        const int mg = 2 * bid + sl;
        const float a = adj[(size_t)(mg * APM + r) * T_ATOMS + (size_t)mg * APM + c];
        S.Abf[sl][r][c] = __float2bfloat16(a + ((r == c) ? 1.0f : 0.0f));
    }
    // layer-0 weights -> bf16 hi/lo (shared), packed bf16x2 stores
    {
        const float2* W2 = reinterpret_cast<const float2*>(W_fp);
        #pragma unroll
        for (int t = 0; t < 16; t++) {
            const int e = tid + t * 128;
            const int d = e >> 5, c2 = e & 31;
            const float2 wv = W2[e];
            const __nv_bfloat162 hi = __floats2bfloat162_rn(wv.x, wv.y);
            const __nv_bfloat162 lo =
                __floats2bfloat162_rn(wv.x - __bfloat162float(hi.x),
                                      wv.y - __bfloat162float(hi.y));
            *reinterpret_cast<__nv_bfloat162*>(&S.Whi[d][2 * c2]) = hi;
            *reinterpret_cast<__nv_bfloat162*>(&S.Wlo[d][2 * c2]) = lo;
        }
    }
    // embedding gather: this warp's 16 atoms (rows 16*half..+15 of mol s)
    #pragma unroll
    for (int q = 0; q < 16; q++) {
        const int atom = 16 * half + q;
        const int f = fp[mm * APM + atom];
        const float x = embed[(size_t)f * DIM + lane];
        const float y = embed[(size_t)f * DIM + lane + 32];
        const __nv_bfloat16 xh = __float2bfloat16(x);
        const __nv_bfloat16 yh = __float2bfloat16(y);
        S.Vhi[s][atom][lane]      = xh;
        S.Vhi[s][atom][lane + 32] = yh;
        S.Vlo[s][atom][lane]      = __float2bfloat16(x - __bfloat162float(xh));
        S.Vlo[s][atom][lane + 32] = __float2bfloat16(y - __bfloat162float(yh));
    }
    __syncthreads();

    // prop A-fragments: loaded once, reused all layers (K=32 -> kt 0,1)
    uint32_t pa[2][4];
    #pragma unroll
    for (int kt = 0; kt < 2; kt++) {
        const int b0 = r0 * 80 + kt * 32 + tig * 4;
        pa[kt][0] = lds_u32(&S.Abf[s][0][0], b0);
        pa[kt][1] = lds_u32(&S.Abf[s][0][0], b0 + 8 * 80);
        pa[kt][2] = lds_u32(&S.Abf[s][0][0], b0 + 16);
        pa[kt][3] = lds_u32(&S.Abf[s][0][0], b0 + 8 * 80 + 16);
    }

    // ================= 3 GNN layers =================
    for (int l = 0; l < LH; l++) {
        // ---- MLP MMA: m16 tile (16 atoms) x 8 n-tiles (64 dims) ------------
        uint32_t Ah[4][4], Al[4][4];
        #pragma unroll
        for (int kt = 0; kt < 4; kt++) {
            const int b0 = r0 * 144 + kt * 32 + tig * 4;
            Ah[kt][0] = lds_u32(&S.Vhi[s][0][0], b0);
            Ah[kt][1] = lds_u32(&S.Vhi[s][0][0], b0 + 8 * 144);
            Ah[kt][2] = lds_u32(&S.Vhi[s][0][0], b0 + 16);
            Ah[kt][3] = lds_u32(&S.Vhi[s][0][0], b0 + 8 * 144 + 16);
            Al[kt][0] = lds_u32(&S.Vlo[s][0][0], b0);
            Al[kt][1] = lds_u32(&S.Vlo[s][0][0], b0 + 8 * 144);
            Al[kt][2] = lds_u32(&S.Vlo[s][0][0], b0 + 16);
            Al[kt][3] = lds_u32(&S.Vlo[s][0][0], b0 + 8 * 144 + 16);
        }
        #pragma unroll
        for (int nt = 0; nt < 8; nt++) {
            float d0 = 0.f, d1 = 0.f, d2 = 0.f, d3 = 0.f;
            #pragma unroll
            for (int kt = 0; kt < 4; kt++) {
                const int rb = (nt * 8 + g4) * 144 + kt * 32 + tig * 4;
                const uint32_t bh0 = lds_u32(&S.Whi[0][0], rb);
                const uint32_t bh1 = lds_u32(&S.Whi[0][0], rb + 16);
                const uint32_t bl0 = lds_u32(&S.Wlo[0][0], rb);
                const uint32_t bl1 = lds_u32(&S.Wlo[0][0], rb + 16);
                MMA_BF16(d0, d1, d2, d3, Ah[kt][0], Ah[kt][1], Ah[kt][2], Ah[kt][3], bh0, bh1);
                MMA_BF16(d0, d1, d2, d3, Al[kt][0], Al[kt][1], Al[kt][2], Al[kt][3], bh0, bh1);
                MMA_BF16(d0, d1, d2, d3, Ah[kt][0], Ah[kt][1], Ah[kt][2], Ah[kt][3], bl0, bl1);
            }
            // bias + relu -> hi/lo transposed tiles hT[s][d][atom]
            const int c0 = nt * 8 + 2 * tig;
            const float h00 = fmaxf(d0 + S.sBias[l * DIM + c0], 0.0f);
            const float h01 = fmaxf(d1 + S.sBias[l * DIM + c0 + 1], 0.0f);
            const float h10 = fmaxf(d2 + S.sBias[l * DIM + c0], 0.0f);
            const float h11 = fmaxf(d3 + S.sBias[l * DIM + c0 + 1], 0.0f);
            const __nv_bfloat16 a0 = __float2bfloat16(h00);
            const __nv_bfloat16 a1 = __float2bfloat16(h01);
            const __nv_bfloat16 a2 = __float2bfloat16(h10);
            const __nv_bfloat16 a3 = __float2bfloat16(h11);
            S.hThi[s][c0][r0]     = a0;
            S.hThi[s][c0 + 1][r0] = a1;
            S.hThi[s][c0][r1]     = a2;
            S.hThi[s][c0 + 1][r1] = a3;
            S.hTlo[s][c0][r0]     = __float2bfloat16(h00 - __bfloat162float(a0));
            S.hTlo[s][c0 + 1][r0] = __float2bfloat16(h01 - __bfloat162float(a1));
            S.hTlo[s][c0][r1]     = __float2bfloat16(h10 - __bfloat162float(a2));
            S.hTlo[s][c0 + 1][r1] = __float2bfloat16(h11 - __bfloat162float(a3));
        }
        __syncthreads();   // hT published; all V/W fragment reads complete

        // prefetch next layer's weights (Whi/Wlo idle until after next barrier)
        if (l + 1 < LH) {
            const float2* Wn2 =
                reinterpret_cast<const float2*>(W_fp + (l + 1) * DIM * DIM);
            #pragma unroll
            for (int t = 0; t < 16; t++) {
                const int e = tid + t * 128;
                const int d = e >> 5, c2 = e & 31;
                const float2 wv = Wn2[e];
                const __nv_bfloat162 hi = __floats2bfloat162_rn(wv.x, wv.y);
                const __nv_bfloat162 lo =
                    __floats2bfloat162_rn(wv.x - __bfloat162float(hi.x),
                                          wv.y - __bfloat162float(hi.y));
                *reinterpret_cast<__nv_bfloat162*>(&S.Whi[d][2 * c2]) = hi;
                *reinterpret_cast<__nv_bfloat162*>(&S.Wlo[d][2 * c2]) = lo;
            }
        }

        // ---- prop MMA: D2 = (A+I) @ (Hhi + Hlo), 8 n-tiles ----------------
        float dr[8][4];
        #pragma unroll
        for (int nt = 0; nt < 8; nt++) {
            float d0 = 0.f, d1 = 0.f, d2 = 0.f, d3 = 0.f;
            #pragma unroll
            for (int kt = 0; kt < 2; kt++) {
                const int rb = (nt * 8 + g4) * 80 + kt * 32 + tig * 4;
                const uint32_t bh0 = lds_u32(&S.hThi[s][0][0], rb);
                const uint32_t bh1 = lds_u32(&S.hThi[s][0][0], rb + 16);
                const uint32_t bl0 = lds_u32(&S.hTlo[s][0][0], rb);
                const uint32_t bl1 = lds_u32(&S.hTlo[s][0][0], rb + 16);
                MMA_BF16(d0, d1, d2, d3, pa[kt][0], pa[kt][1], pa[kt][2], pa[kt][3], bh0, bh1);
                MMA_BF16(d0, d1, d2, d3, pa[kt][0], pa[kt][1], pa[kt][2], pa[kt][3], bl0, bl1);
            }
            dr[nt][0] = d0; dr[nt][1] = d1; dr[nt][2] = d2; dr[nt][3] = d3;
        }

        // ---- warp-local L2 norms (tig group spans all 64 dims) ------------
        float ss0 = 0.f, ss1 = 0.f;
        #pragma unroll
        for (int nt = 0; nt < 8; nt++) {
            ss0 = fmaf(dr[nt][0], dr[nt][0], fmaf(dr[nt][1], dr[nt][1], ss0));
            ss1 = fmaf(dr[nt][2], dr[nt][2], fmaf(dr[nt][3], dr[nt][3], ss1));
        }
        ss0 += __shfl_xor_sync(0xffffffffu, ss0, 1);
        ss0 += __shfl_xor_sync(0xffffffffu, ss0, 2);
        ss1 += __shfl_xor_sync(0xffffffffu, ss1, 1);
        ss1 += __shfl_xor_sync(0xffffffffu, ss1, 2);
        const float inv0 = rsqrtf(fmaxf(ss0, 1e-24f));   // 1/max(||.||,1e-12)
        const float inv1 = rsqrtf(fmaxf(ss1, 1e-24f));

        if (l < LH - 1) {
            // normalized v -> split bf16 back into Vhi/Vlo (bf16x2 stores)
            #pragma unroll
            for (int nt = 0; nt < 8; nt++) {
                const int c0 = nt * 8 + 2 * tig;
                const float v00 = dr[nt][0] * inv0, v01 = dr[nt][1] * inv0;
                const float v10 = dr[nt][2] * inv1, v11 = dr[nt][3] * inv1;
                const __nv_bfloat162 hiA = __floats2bfloat162_rn(v00, v01);
                const __nv_bfloat162 hiB = __floats2bfloat162_rn(v10, v11);
                const __nv_bfloat162 loA =
                    __floats2bfloat162_rn(v00 - __bfloat162float(hiA.x),
                                          v01 - __bfloat162float(hiA.y));
                const __nv_bfloat162 loB =
                    __floats2bfloat162_rn(v10 - __bfloat162float(hiB.x),
                                          v11 - __bfloat162float(hiB.y));
                *reinterpret_cast<__nv_bfloat162*>(&S.Vhi[s][r0][c0]) = hiA;
                *reinterpret_cast<__nv_bfloat162*>(&S.Vhi[s][r1][c0]) = hiB;
                *reinterpret_cast<__nv_bfloat162*>(&S.Vlo[s][r0][c0]) = loA;
                *reinterpret_cast<__nv_bfloat162*>(&S.Vlo[s][r1][c0]) = loB;
            }
            __syncthreads();   // V published; hT free; W prefetch visible
        } else {
            // ---- molecular sum from fragments ------------------------------
            // per-col partial over this thread's 2 rows, then sum across g4
            // (shfl xor 4/8/16) -> 16-atom partial for this warp's half.
            float colsum[8][2];
            #pragma unroll
            for (int nt = 0; nt < 8; nt++) {
                colsum[nt][0] = dr[nt][0] * inv0 + dr[nt][2] * inv1;
                colsum[nt][1] = dr[nt][1] * inv0 + dr[nt][3] * inv1;
            }
            #pragma unroll
            for (int nt = 0; nt < 8; nt++) {
                #pragma unroll
                for (int h = 0; h < 2; h++) {
                    float v = colsum[nt][h];
                    v += __shfl_xor_sync(0xffffffffu, v, 4);
                    v += __shfl_xor_sync(0xffffffffu, v, 8);
                    v += __shfl_xor_sync(0xffffffffu, v, 16);
                    colsum[nt][h] = v;
                }
            }
            if (g4 == 0) {
                #pragma unroll
                for (int nt = 0; nt < 8; nt++) {
                    const int c0 = nt * 8 + 2 * tig;
                    S.molP[s][half][c0]     = colsum[nt][0];
                    S.molP[s][half][c0 + 1] = colsum[nt][1];
                }
            }
            __syncthreads();
        }
    }

    // ================= output MLP (2 mols x 64 dims on 128 threads) =========
    {
        const int so = tid >> 6;
        const int d  = tid & 63;
        S.molA[so][d] = S.molP[so][0][d] + S.molP[so][1][d];
    }
    __syncthreads();
    {
        const int so = tid >> 6;
        const int d  = tid & 63;
        const float* Wr = W_out + d * DIM;
        float a = b_out[d];
        #pragma unroll
        for (int k = 0; k < DIM; k += 4) {
            const float4 w4 = *reinterpret_cast<const float4*>(&Wr[k]);
            a += S.molA[so][k] * w4.x + S.molA[so][k + 1] * w4.y
               + S.molA[so][k + 2] * w4.z + S.molA[so][k + 3] * w4.w;
        }
        S.molB[so][d] = fmaxf(a, 0.0f);
    }
    __syncthreads();
    {
        const int so = tid >> 6;
        const int d  = tid & 63;
        const float* Wr = W_out + DIM * DIM + d * DIM;
        float a = b_out[DIM + d];
        #pragma unroll
        for (int k = 0; k < DIM; k += 4) {
            const float4 w4 = *reinterpret_cast<const float4*>(&Wr[k]);
            a += S.molB[so][k] * w4.x + S.molB[so][k + 1] * w4.y
               + S.molB[so][k + 2] * w4.z + S.molB[so][k + 3] * w4.w;
        }
        S.molA[so][d] = fmaxf(a, 0.0f);
    }
    __syncthreads();

    // ================= final property: warp 0 -> mol 0, warp 1 -> mol 1 =====
    if (g < 2) {
        float t2 = S.molA[g][lane] * W_prop[lane]
                 + S.molA[g][lane + 32] * W_prop[lane + 32];
        #pragma unroll
        for (int o = 16; o; o >>= 1)
            t2 += __shfl_xor_sync(0xffffffffu, t2, o);
        if (lane == 0) out[2 * bid + g] = t2 + b_prop[0];
    }
}

extern "C" void kernel_launch(void* const* d_in, const int* in_sizes, int n_in,
                              void* d_out, int out_size)
{
    // metadata order: fingerprints, adjacency, segment_ids, embed,
    //                 W_fp, b_fp, W_out, b_out, W_prop, b_prop
    const int*   fp     = (const int*)  d_in[0];
    const float* adj    = (const float*)d_in[1];
    // d_in[2] = segment_ids: repeat(arange(256), 32), used implicitly
    const float* embed  = (const float*)d_in[3];
    const float* W_fp   = (const float*)d_in[4];
    const float* b_fp   = (const float*)d_in[5];
    const float* W_out  = (const float*)d_in[6];
    const float* b_out  = (const float*)d_in[7];
    const float* W_prop = (const float*)d_in[8];
    const float* b_prop = (const float*)d_in[9];
    float* outp = (float*)d_out;

    const int smem_bytes = (int)sizeof(SmemLayout);   // ~65 KB -> dynamic
    cudaFuncSetAttribute(gnn_mol_kernel,
                         cudaFuncAttributeMaxDynamicSharedMemorySize, smem_bytes);

    gnn_mol_kernel<<<B_MOL / 2, 128, smem_bytes>>>(fp, adj, embed, W_fp, b_fp,
                                                   W_out, b_out, W_prop, b_prop,
                                                   outp);
}